// round 5
// baseline (speedup 1.0000x reference)
#include <cuda_runtime.h>
#include <stdint.h>

// Scratch (device allocation is forbidden anywhere).
#define MAX_B 8192
#define SPLIT 2                         // CTAs per user (row-halved)
__device__ float        g_partial[MAX_B * SPLIT];
__device__ unsigned int g_done_count = 0;   // last CTA resets -> graph-replay safe

#define P_MAX 256          // P = 200 here
#define NTHREADS 256
#define NWARPS (NTHREADS / 32)
#define RBLK 8             // rows per warp iteration: 2 packed combine-4 quads
#define ROWSTEP (RBLK * NWARPS)         // 64 rows per CTA pass
#define ROWSTRIDE (ROWSTEP * SPLIT)     // 128: stride between this CTA's passes

__device__ __forceinline__ float fast_rcp(float x) {
    float r;
    asm("rcp.approx.f32 %0, %1;" : "=f"(r) : "f"(x));
    return r;
}

// ---- packed f32x2 helpers (sm_103a) ----
__device__ __forceinline__ uint64_t pk2(float lo, float hi) {
    uint64_t r;
    asm("mov.b64 %0, {%1, %2};" : "=l"(r) : "r"(__float_as_uint(lo)), "r"(__float_as_uint(hi)));
    return r;
}
__device__ __forceinline__ void upk2(uint64_t v, float& lo, float& hi) {
    uint32_t a, b;
    asm("mov.b64 {%0, %1}, %2;" : "=r"(a), "=r"(b) : "l"(v));
    lo = __uint_as_float(a); hi = __uint_as_float(b);
}
__device__ __forceinline__ uint64_t addx2(uint64_t a, uint64_t b) {
    uint64_t r; asm("add.rn.f32x2 %0, %1, %2;" : "=l"(r) : "l"(a), "l"(b)); return r;
}
__device__ __forceinline__ uint64_t mulx2(uint64_t a, uint64_t b) {
    uint64_t r; asm("mul.rn.f32x2 %0, %1, %2;" : "=l"(r) : "l"(a), "l"(b)); return r;
}
__device__ __forceinline__ uint64_t fmax2(uint64_t a, uint64_t b, uint64_t c) {
    uint64_t r; asm("fma.rn.f32x2 %0, %1, %2, %3;" : "=l"(r) : "l"(a), "l"(b), "l"(c)); return r;
}

// Two CTAs per user b (half h in {0,1} owns row-blocks offset 64h, stride 128):
//   partial[2b+h] = sum over its rows i, all cols j<c of sigmoid(pos[i]-neg[j])
// sigmoid(p-n) = e^p/(e^p+e^n). Weighted combine-4 over rows at one column e:
//   sum_r ep_r/(ep_r+e) = [wx*(ep0*v+ep1*u) + uv*(ep2*x+ep3*w)] * rcp(u*v*w*x)
// -> 1 MUFU per 4 pairs, weights folded into the numerator. Two row-quads ride
// the f32x2 halves: 8 pairs / 14 FMA-pipe instrs / 2 MUFU per warp-iteration.
__global__ void __launch_bounds__(NTHREADS, 4)
sauc_user_kernel(const float* __restrict__ scores_pos,
                 const float* __restrict__ scores_neg,
                 const int*   __restrict__ pos_counts,
                 float* __restrict__ out,
                 int B, int P)
{
    const int b    = blockIdx.x >> 1;
    const int half = blockIdx.x & 1;

    __shared__ float s_ep[P_MAX];
    __shared__ float s_en[P_MAX];
    __shared__ float s_warp[NWARPS];
    __shared__ int   s_is_last;

    const int tid  = threadIdx.x;
    const int lane = tid & 31;
    const int wid  = tid >> 5;

    const int c = pos_counts[b];

    const float* pp = scores_pos + (size_t)b * P;
    const float* pn = scores_neg + (size_t)b * P;
    for (int k = tid; k < c; k += NTHREADS) {
        s_ep[k] = __expf(pp[k]);
        s_en[k] = __expf(pn[k]);
    }
    __syncthreads();

    // Warp w of half h owns row blocks i0 = RBLK*w + 64*h, stepping 128.
    // Lane l owns columns j = l, l+32, ...
    uint64_t acc2 = 0ull;                    // packed {0.0f, 0.0f}
    for (int i0 = RBLK * wid + ROWSTEP * half; i0 < c; i0 += ROWSTRIDE) {
        // Rows past c get ep = 0: their weight terms vanish exactly and
        // u..x stay > 0 (no NaN/Inf anywhere).
        float ep[RBLK];
        #pragma unroll
        for (int r = 0; r < RBLK; r++)
            ep[r] = (i0 + r < c) ? s_ep[i0 + r] : 0.0f;
        // f32x2 halves: quad {0..3} | quad {4..7}
        const uint64_t epA = pk2(ep[0], ep[4]);
        const uint64_t epB = pk2(ep[1], ep[5]);
        const uint64_t epC = pk2(ep[2], ep[6]);
        const uint64_t epD = pk2(ep[3], ep[7]);

        for (int j = lane; j < c; j += 32) {
            const float e  = s_en[j];
            const uint64_t eP = pk2(e, e);
            const uint64_t u  = addx2(epA, eP);
            const uint64_t v  = addx2(epB, eP);
            const uint64_t w  = addx2(epC, eP);
            const uint64_t x  = addx2(epD, eP);
            const uint64_t uv = mulx2(u, v);
            const uint64_t wx = mulx2(w, x);
            const uint64_t A  = fmax2(epB, u, mulx2(epA, v));   // ep0*v + ep1*u
            const uint64_t Bn = fmax2(epD, w, mulx2(epC, x));   // ep2*x + ep3*w
            const uint64_t N  = fmax2(Bn, uv, mulx2(A, wx));    // A*wx + Bn*uv
            const uint64_t Dp = mulx2(uv, wx);
            float d0, d1; upk2(Dp, d0, d1);
            const uint64_t R = pk2(fast_rcp(d0), fast_rcp(d1));
            acc2 = fmax2(N, R, acc2);
        }
    }

    float aLo, aHi; upk2(acc2, aLo, aHi);
    float acc = aLo + aHi;

    // Fixed-order warp + block reduction (deterministic).
    #pragma unroll
    for (int o = 16; o > 0; o >>= 1)
        acc += __shfl_down_sync(0xFFFFFFFFu, acc, o);
    if (lane == 0) s_warp[wid] = acc;
    __syncthreads();

    if (tid == 0) {
        float psum = 0.0f;
        #pragma unroll
        for (int w = 0; w < NWARPS; w++) psum += s_warp[w];
        g_partial[blockIdx.x] = psum;
        __threadfence();
        unsigned int v = atomicAdd(&g_done_count, 1u);
        s_is_last = (v == (unsigned int)(gridDim.x - 1));
    }
    __syncthreads();

    // Elected last CTA: per-user losses + mean, fixed index order, then rearm.
    if (s_is_last) {
        volatile const float* parts = g_partial;
        float a = 0.0f;
        for (int u = tid; u < B; u += NTHREADS) {
            const float ps = parts[2 * u] + parts[2 * u + 1];
            const float p  = (float)pos_counts[u];
            a += 1.0f - ps / (p * p);
        }
        __shared__ float s_red[NTHREADS];
        s_red[tid] = a;
        __syncthreads();
        #pragma unroll
        for (int o = NTHREADS / 2; o > 0; o >>= 1) {
            if (tid < o) s_red[tid] += s_red[tid + o];
            __syncthreads();
        }
        if (tid == 0) {
            out[0] = s_red[0] / (float)B;
            g_done_count = 0;   // rearm for next graph replay
        }
    }
}

extern "C" void kernel_launch(void* const* d_in, const int* in_sizes, int n_in,
                              void* d_out, int out_size)
{
    const float* scores_pos = (const float*)d_in[0];
    const float* scores_neg = (const float*)d_in[1];
    const int*   pos_counts = (const int*)  d_in[2];
    float*       out        = (float*)d_out;

    const int B = in_sizes[2];       // 4096
    const int P = in_sizes[0] / B;   // 200

    sauc_user_kernel<<<B * SPLIT, NTHREADS>>>(scores_pos, scores_neg, pos_counts, out, B, P);
}

// round 13
// speedup vs baseline: 1.2033x; 1.2033x over previous
#include <cuda_runtime.h>
#include <stdint.h>

// Scratch (device allocation is forbidden anywhere).
#define MAX_B 8192
__device__ float        g_partial[MAX_B];
__device__ unsigned int g_done_count = 0;   // last CTA resets -> graph-replay safe

#define P_MAX 256          // P = 200 here
#define NTHREADS 256
#define NWARPS (NTHREADS / 32)
#define RBLK 16            // rows per warp iteration = 4 independent combine-4 quads

__device__ __forceinline__ float fast_rcp(float x) {
    float r;
    asm("rcp.approx.f32 %0, %1;" : "=f"(r) : "f"(x));
    return r;
}

// Weighted combine-4: sum_r p_r/(p_r+e) for 4 rows with ONE reciprocal.
//   u..x = p_r + e ;  A = p0*v + p1*u ;  Bn = p2*x + p3*w
//   sum  = (A*wx + Bn*uv) * rcp(uv*wx)
// 14 scalar FMA-pipe ops + 1 MUFU per 4 pairs. p_r = 0 rows contribute exactly 0.
__device__ __forceinline__ float quad4(float p0, float p1, float p2, float p3,
                                       float e, float a) {
    const float u  = p0 + e;
    const float v  = p1 + e;
    const float w  = p2 + e;
    const float x  = p3 + e;
    const float uv = u * v;
    const float wx = w * x;
    const float A  = fmaf(p1, u, p0 * v);
    const float Bn = fmaf(p3, w, p2 * x);
    const float N  = fmaf(A, wx, Bn * uv);
    const float R  = fast_rcp(uv * wx);
    return fmaf(N, R, a);
}

// One CTA per user b:
//   partial[b] = sum_{i,j<c} sigmoid(pos[i]-neg[j]),  sigmoid(p-n)=e^p/(e^p+e^n)
// Warp w owns row blocks i0 = 16w, stride 128. Lane l owns columns j = l, l+32...
// Four independent quads per column step give the ILP to hide RCP(16); the
// software-pipelined prefetch of e hides LDS(29) behind the current iteration.
__global__ void __launch_bounds__(NTHREADS, 4)
sauc_user_kernel(const float* __restrict__ scores_pos,
                 const float* __restrict__ scores_neg,
                 const int*   __restrict__ pos_counts,
                 float* __restrict__ out,
                 int B, int P)
{
    const int b = blockIdx.x;

    __shared__ float s_ep[P_MAX];
    __shared__ float s_en[P_MAX];
    __shared__ float s_warp[NWARPS];
    __shared__ int   s_is_last;

    const int tid  = threadIdx.x;
    const int lane = tid & 31;
    const int wid  = tid >> 5;

    const int c = pos_counts[b];

    const float* pp = scores_pos + (size_t)b * P;
    const float* pn = scores_neg + (size_t)b * P;
    for (int k = tid; k < c; k += NTHREADS) {
        s_ep[k] = __expf(pp[k]);
        s_en[k] = __expf(pn[k]);
    }
    __syncthreads();

    float acc = 0.0f;
    for (int i0 = RBLK * wid; i0 < c; i0 += RBLK * NWARPS) {
        // Rows past c get ep = 0: weight terms vanish exactly, u..x stay > 0.
        float ep[RBLK];
        #pragma unroll
        for (int r = 0; r < RBLK; r++)
            ep[r] = (i0 + r < c) ? s_ep[i0 + r] : 0.0f;

        float a0 = 0.0f, a1 = 0.0f, a2 = 0.0f, a3 = 0.0f;  // 4 indep chains
        int j = lane;
        if (j < c) {
            float e = s_en[j];                    // prologue load
            for (; j + 32 < c; j += 32) {
                const float enext = s_en[j + 32]; // prefetch next column
                a0 = quad4(ep[0],  ep[1],  ep[2],  ep[3],  e, a0);
                a1 = quad4(ep[4],  ep[5],  ep[6],  ep[7],  e, a1);
                a2 = quad4(ep[8],  ep[9],  ep[10], ep[11], e, a2);
                a3 = quad4(ep[12], ep[13], ep[14], ep[15], e, a3);
                e = enext;
            }
            // epilogue column
            a0 = quad4(ep[0],  ep[1],  ep[2],  ep[3],  e, a0);
            a1 = quad4(ep[4],  ep[5],  ep[6],  ep[7],  e, a1);
            a2 = quad4(ep[8],  ep[9],  ep[10], ep[11], e, a2);
            a3 = quad4(ep[12], ep[13], ep[14], ep[15], e, a3);
        }
        acc += (a0 + a1) + (a2 + a3);
    }

    // Fixed-order warp + block reduction (deterministic).
    #pragma unroll
    for (int o = 16; o > 0; o >>= 1)
        acc += __shfl_down_sync(0xFFFFFFFFu, acc, o);
    if (lane == 0) s_warp[wid] = acc;
    __syncthreads();

    if (tid == 0) {
        float psum = 0.0f;
        #pragma unroll
        for (int w = 0; w < NWARPS; w++) psum += s_warp[w];
        g_partial[b] = psum;
        __threadfence();
        unsigned int v = atomicAdd(&g_done_count, 1u);
        s_is_last = (v == (unsigned int)(gridDim.x - 1));
    }
    __syncthreads();

    // Elected last CTA: per-user losses + mean in fixed index order, then rearm.
    if (s_is_last) {
        volatile const float* parts = g_partial;
        float a = 0.0f;
        for (int u = tid; u < B; u += NTHREADS) {
            const float p = (float)pos_counts[u];
            a += 1.0f - parts[u] / (p * p);
        }
        __shared__ float s_red[NTHREADS];
        s_red[tid] = a;
        __syncthreads();
        #pragma unroll
        for (int o = NTHREADS / 2; o > 0; o >>= 1) {
            if (tid < o) s_red[tid] += s_red[tid + o];
            __syncthreads();
        }
        if (tid == 0) {
            out[0] = s_red[0] / (float)B;
            g_done_count = 0;   // rearm for next graph replay
        }
    }
}

extern "C" void kernel_launch(void* const* d_in, const int* in_sizes, int n_in,
                              void* d_out, int out_size)
{
    const float* scores_pos = (const float*)d_in[0];
    const float* scores_neg = (const float*)d_in[1];
    const int*   pos_counts = (const int*)  d_in[2];
    float*       out        = (float*)d_out;

    const int B = in_sizes[2];       // 4096
    const int P = in_sizes[0] / B;   // 200

    sauc_user_kernel<<<B, NTHREADS>>>(scores_pos, scores_neg, pos_counts, out, B, P);
}

// round 16
// speedup vs baseline: 1.2462x; 1.0356x over previous
#include <cuda_runtime.h>
#include <stdint.h>

// Scratch (device allocation is forbidden anywhere).
#define MAX_B 8192
__device__ float        g_partial[MAX_B];
__device__ unsigned int g_done_count = 0;   // last CTA resets -> graph-replay safe

#define NTHREADS 256
#define WPB 8               // warps per block = users per block
#define P_PAD 208           // per-warp padded column storage (mult of 8, 16B-aligned)
#define EPAD 1048576.0f     // 2^20 column pad: spurious 1/(p+2^20) ~ 1e-6, no overflow

__device__ __forceinline__ float fast_rcp(float x) {
    float r;
    asm("rcp.approx.f32 %0, %1;" : "=f"(r) : "f"(x));
    return r;
}

// combine-4 over columns for one row value p (>0 real, ==0 padded row):
//   1/(p+e0)+1/(p+e1)+1/(p+e2)+1/(p+e3) = ((u+v)*wx + (w+x)*uv) * rcp(uv*wx)
// 12 FMA-pipe ops + 1 MUFU per 4 pairs.
__device__ __forceinline__ float col4(float p, float4 e, float racc) {
    const float u  = p + e.x;
    const float v  = p + e.y;
    const float w  = p + e.z;
    const float x  = p + e.w;
    const float uv = u * v;
    const float wx = w * x;
    const float N  = fmaf(u + v, wx, (w + x) * uv);
    return fmaf(N, fast_rcp(uv * wx), racc);
}

// One WARP per user u:
//   partial[u] = sum_{i,j<c} sigmoid(pos[i]-neg[j]),  sigmoid(p-n)=e^p/(e^p+e^n)
// Lane l owns rows l, l+32, ... (ep in registers, 0-padded => exact 0 contribution).
// Columns exp'd into this warp's shared row, padded to mult-of-8 with EPAD.
// Inner loop: 2 rows x 8 columns -> 4 independent rcp chains, 2x LDS.128 broadcast.
__global__ void __launch_bounds__(NTHREADS, 4)
sauc_warp_kernel(const float* __restrict__ scores_pos,
                 const float* __restrict__ scores_neg,
                 const int*   __restrict__ pos_counts,
                 float* __restrict__ out,
                 int B, int P)
{
    __shared__ __align__(16) float s_en[WPB][P_PAD];
    __shared__ float s_red[NTHREADS];
    __shared__ int   s_is_last;

    const int tid  = threadIdx.x;
    const int lane = tid & 31;
    const int wid  = tid >> 5;
    const int u    = blockIdx.x * WPB + wid;

    const int c  = (u < B) ? pos_counts[u] : 0;
    const int K  = (c + 31) >> 5;        // row groups per lane (0..7)
    const int c8 = (c + 7) & ~7;         // columns padded to multiple of 8

    const float* pp = scores_pos + (size_t)u * P;
    const float* pn = scores_neg + (size_t)u * P;

    float ep[7];
    #pragma unroll
    for (int k = 0; k < 7; k++) {
        const int idx = lane + 32 * k;
        const bool real = (idx < c);
        ep[k] = real ? __expf(pp[idx]) : 0.0f;
        if (idx < c8) s_en[wid][idx] = real ? __expf(pn[idx]) : EPAD;
    }
    __syncwarp();

    const float* en = s_en[wid];
    float acc = 0.0f;

    // Process a pair of row registers against all (padded) columns.
    auto rowpair = [&](float p0, float p1) {
        float r0 = 0.0f, r0b = 0.0f, r1 = 0.0f, r1b = 0.0f;
        for (int j = 0; j < c8; j += 8) {
            const float4 eA = *reinterpret_cast<const float4*>(en + j);
            const float4 eB = *reinterpret_cast<const float4*>(en + j + 4);
            r0  = col4(p0, eA, r0);
            r0b = col4(p0, eB, r0b);
            r1  = col4(p1, eA, r1);
            r1b = col4(p1, eB, r1b);
        }
        acc = fmaf(p0, r0 + r0b, acc);   // row weight applied once per row
        acc = fmaf(p1, r1 + r1b, acc);
    };

    rowpair(ep[0], ep[1]);               // K >= 1 always (c >= 1)
    if (K > 2) rowpair(ep[2], ep[3]);
    if (K > 4) rowpair(ep[4], ep[5]);
    if (K > 6) rowpair(ep[6], 0.0f);

    // Fixed-order warp reduction; lane 0 publishes this user's pair_sum.
    #pragma unroll
    for (int o = 16; o > 0; o >>= 1)
        acc += __shfl_down_sync(0xFFFFFFFFu, acc, o);
    if (lane == 0 && u < B) g_partial[u] = acc;

    __syncthreads();
    if (tid == 0) {
        __threadfence();
        unsigned int v = atomicAdd(&g_done_count, 1u);
        s_is_last = (v == (unsigned int)(gridDim.x - 1));
    }
    __syncthreads();

    // Elected last CTA: per-user losses + mean in fixed index order, then rearm.
    if (s_is_last) {
        volatile const float* parts = g_partial;
        float a = 0.0f;
        for (int i = tid; i < B; i += NTHREADS) {
            const float p = (float)pos_counts[i];
            a += 1.0f - parts[i] / (p * p);
        }
        s_red[tid] = a;
        __syncthreads();
        #pragma unroll
        for (int o = NTHREADS / 2; o > 0; o >>= 1) {
            if (tid < o) s_red[tid] += s_red[tid + o];
            __syncthreads();
        }
        if (tid == 0) {
            out[0] = s_red[0] / (float)B;
            g_done_count = 0;   // rearm for next graph replay
        }
    }
}

extern "C" void kernel_launch(void* const* d_in, const int* in_sizes, int n_in,
                              void* d_out, int out_size)
{
    const float* scores_pos = (const float*)d_in[0];
    const float* scores_neg = (const float*)d_in[1];
    const int*   pos_counts = (const int*)  d_in[2];
    float*       out        = (float*)d_out;

    const int B = in_sizes[2];       // 4096
    const int P = in_sizes[0] / B;   // 200

    const int grid = (B + WPB - 1) / WPB;   // 512
    sauc_warp_kernel<<<grid, NTHREADS>>>(scores_pos, scores_neg, pos_counts, out, B, P);
}